// round 1
// baseline (speedup 1.0000x reference)
#include <cuda_runtime.h>
#include <cstdint>

#define NN 30000          // nodes per graph
#define DD 768            // feature dim
#define NE 480000         // edges per graph
#define K2 (2*DD)         // GEMM K = 1536

// ---------------- scratch (static device memory; no allocs) ----------------
__device__ float g_agg[(size_t)NN * DD];     // 92 MB: layer-1 mean aggregate (pre-scaled by inv_cnt)
__device__ float g_h[(size_t)NN * DD];       // 92 MB: layer-1 output
__device__ int   g_cnt[NN];
__device__ float g_inv[NN];
__device__ int   g_start[NN + 1];
__device__ int   g_cursor[NN];
__device__ int   g_sorted[NE];
__device__ float g_colsum[DD];               // sum over nodes of h
__device__ float g_s2[DD];                   // sum_i inv[i] * sum_seg(i) h[src]  (= N*mean(agg2))
__device__ float g_agg2var[DD];
__device__ float g_rowvar[DD];               // h[var_idx]
__device__ float g_emb1[DD], g_emb2[DD], g_embt[DD];
__device__ float g_feats[3 * DD];
__device__ float g_outv[DD], g_tgt[DD];

// ---------------- small helpers ----------------
__device__ __forceinline__ unsigned long long fma2(unsigned long long a,
                                                   unsigned long long b,
                                                   unsigned long long c) {
    unsigned long long d;
    asm("fma.rn.f32x2 %0, %1, %2, %3;" : "=l"(d) : "l"(a), "l"(b), "l"(c));
    return d;
}
__device__ __forceinline__ unsigned long long dup2(float a) {
    unsigned long long d;
    asm("mov.b64 %0, {%1, %1};" : "=l"(d) : "f"(a));
    return d;
}

// ---------------- graph prep ----------------
__global__ void zero_graph_kernel() {
    int t = blockIdx.x * 256 + threadIdx.x;
    if (t < NN) g_cnt[t] = 0;
    if (t < DD) { g_colsum[t] = 0.f; g_s2[t] = 0.f; g_agg2var[t] = 0.f; }
}

__global__ void count_kernel(const int* __restrict__ ei) {
    int e = blockIdx.x * 256 + threadIdx.x;
    if (e < NE) atomicAdd(&g_cnt[ei[NE + e]], 1);
}

__global__ void prefix_kernel() {   // 1 block, 1024 threads
    __shared__ int sh[1024];
    __shared__ int carry;
    int tid = threadIdx.x;
    if (tid == 0) carry = 0;
    __syncthreads();
    for (int base = 0; base < NN; base += 1024) {
        int i = base + tid;
        int v = (i < NN) ? g_cnt[i] : 0;
        int xv = v;
        #pragma unroll
        for (int off = 1; off < 1024; off <<= 1) {
            sh[tid] = xv; __syncthreads();
            if (tid >= off) xv += sh[tid - off];
            __syncthreads();
        }
        int incl = xv + carry;
        if (i < NN) {
            int excl = incl - v;
            g_start[i] = excl;
            g_cursor[i] = excl;
            g_inv[i] = 1.0f / (float)max(v, 1);
        }
        __syncthreads();
        if (tid == 1023) carry = incl;
        __syncthreads();
    }
    if (tid == 0) g_start[NN] = carry;
}

__global__ void place_kernel(const int* __restrict__ ei) {
    int e = blockIdx.x * 256 + threadIdx.x;
    if (e < NE) {
        int s = ei[e], t = ei[NE + e];
        int pos = atomicAdd(&g_cursor[t], 1);
        g_sorted[pos] = s;
    }
}

// ---------------- layer-1 aggregation: gather by dst segment ----------------
// grid (3750, 6), block 256: one warp per node, 128-col chunk per blockIdx.y
__global__ void gather_agg_kernel(const float* __restrict__ x) {
    int warp = threadIdx.x >> 5, lane = threadIdx.x & 31;
    int node = blockIdx.x * 8 + warp;
    int d = blockIdx.y * 128 + lane * 4;
    int p0 = g_start[node], p1 = g_start[node + 1];
    float4 acc = make_float4(0.f, 0.f, 0.f, 0.f);
    int p = p0;
    for (; p + 4 <= p1; p += 4) {
        int s0 = g_sorted[p], s1 = g_sorted[p+1], s2 = g_sorted[p+2], s3 = g_sorted[p+3];
        float4 v0 = *(const float4*)(x + (size_t)s0 * DD + d);
        float4 v1 = *(const float4*)(x + (size_t)s1 * DD + d);
        float4 v2 = *(const float4*)(x + (size_t)s2 * DD + d);
        float4 v3 = *(const float4*)(x + (size_t)s3 * DD + d);
        acc.x += v0.x + v1.x + v2.x + v3.x;
        acc.y += v0.y + v1.y + v2.y + v3.y;
        acc.z += v0.z + v1.z + v2.z + v3.z;
        acc.w += v0.w + v1.w + v2.w + v3.w;
    }
    for (; p < p1; p++) {
        int s = g_sorted[p];
        float4 v = *(const float4*)(x + (size_t)s * DD + d);
        acc.x += v.x; acc.y += v.y; acc.z += v.z; acc.w += v.w;
    }
    float inv = g_inv[node];
    acc.x *= inv; acc.y *= inv; acc.z *= inv; acc.w *= inv;
    *(float4*)(g_agg + (size_t)node * DD + d) = acc;
}

// ---------------- fused layer-1 GEMM:  h = relu([agg | x] @ [Wl|Wr]^T + b) --
// M=30000, N=768, K=1536. 128x128x16 tile, 256 thr, 8x8 micro via fp32x2 FFMA2.
// Epilogue also accumulates column sums of h into g_colsum.
#define ASTR 132
__global__ __launch_bounds__(256, 2)
void gemm_relu_kernel(const float* __restrict__ x,
                      const float* __restrict__ Wl, const float* __restrict__ bias,
                      const float* __restrict__ Wr) {
    __shared__ float As[16][ASTR];
    __shared__ float Bs[16][ASTR];
    __shared__ float scol[128];

    const int tid = threadIdx.x;
    const int m_block = blockIdx.x * 128;
    const int n_block = blockIdx.y * 128;

    if (tid < 128) scol[tid] = 0.f;

    const int ls_r = tid >> 2;
    const int ls_k = (tid & 3) * 4;

    const int warp = tid >> 5, lane = tid & 31;
    const int wm = warp & 3, wn = warp >> 2;
    const int lm = lane & 3, ln = lane >> 2;
    const int tm = wm * 32 + lm * 4;        // rows tm..tm+3 and tm+16..tm+19
    const int tn = wn * 64 + ln * 4;        // cols tn..tn+3 and tn+32..tn+35

    unsigned long long acc[32];
    #pragma unroll
    for (int i = 0; i < 32; i++) acc[i] = 0ULL;

    for (int k0 = 0; k0 < K2; k0 += 16) {
        __syncthreads();
        const int kg = k0 + ls_k;
        // stage A (two 64-row halves)
        #pragma unroll
        for (int rr = 0; rr < 2; rr++) {
            int r = ls_r + rr * 64;
            int row = m_block + r;
            float4 v = make_float4(0.f, 0.f, 0.f, 0.f);
            if (row < NN) {
                if (kg < DD) v = *(const float4*)(g_agg + (size_t)row * DD + kg);
                else         v = *(const float4*)(x + (size_t)row * DD + (kg - DD));
            }
            As[ls_k + 0][r] = v.x; As[ls_k + 1][r] = v.y;
            As[ls_k + 2][r] = v.z; As[ls_k + 3][r] = v.w;
        }
        // stage B: Wcat[j,k] = k<768 ? Wl[j,k] : Wr[j,k-768]
        #pragma unroll
        for (int rr = 0; rr < 2; rr++) {
            int j = ls_r + rr * 64;
            int col = n_block + j;
            float4 v;
            if (kg < DD) v = *(const float4*)(Wl + (size_t)col * DD + kg);
            else         v = *(const float4*)(Wr + (size_t)col * DD + (kg - DD));
            Bs[ls_k + 0][j] = v.x; Bs[ls_k + 1][j] = v.y;
            Bs[ls_k + 2][j] = v.z; Bs[ls_k + 3][j] = v.w;
        }
        __syncthreads();
        #pragma unroll
        for (int kk = 0; kk < 16; kk++) {
            float4 a0 = *(const float4*)&As[kk][tm];
            float4 a1 = *(const float4*)&As[kk][tm + 16];
            float4 b0 = *(const float4*)&Bs[kk][tn];
            float4 b1 = *(const float4*)&Bs[kk][tn + 32];
            const unsigned long long* b0p = reinterpret_cast<const unsigned long long*>(&b0);
            const unsigned long long* b1p = reinterpret_cast<const unsigned long long*>(&b1);
            unsigned long long bp0 = b0p[0], bp1 = b0p[1], bp2 = b1p[0], bp3 = b1p[1];
            float av[8] = {a0.x, a0.y, a0.z, a0.w, a1.x, a1.y, a1.z, a1.w};
            #pragma unroll
            for (int i = 0; i < 8; i++) {
                unsigned long long ad = dup2(av[i]);
                acc[i*4+0] = fma2(ad, bp0, acc[i*4+0]);
                acc[i*4+1] = fma2(ad, bp1, acc[i*4+1]);
                acc[i*4+2] = fma2(ad, bp2, acc[i*4+2]);
                acc[i*4+3] = fma2(ad, bp3, acc[i*4+3]);
            }
        }
    }

    // epilogue: bias + relu, store h, per-thread column partial sums
    float bj[8];
    #pragma unroll
    for (int c = 0; c < 4; c++) {
        bj[c]     = bias[n_block + tn + c];
        bj[4 + c] = bias[n_block + tn + 32 + c];
    }
    float csum[8] = {0,0,0,0,0,0,0,0};
    #pragma unroll
    for (int i = 0; i < 8; i++) {
        int r = tm + ((i < 4) ? i : (16 + i - 4));
        int row = m_block + r;
        if (row >= NN) continue;
        float2 p0 = *(float2*)&acc[i*4+0];
        float2 p1 = *(float2*)&acc[i*4+1];
        float2 p2 = *(float2*)&acc[i*4+2];
        float2 p3 = *(float2*)&acc[i*4+3];
        float4 w0, w1;
        w0.x = fmaxf(p0.x + bj[0], 0.f); w0.y = fmaxf(p0.y + bj[1], 0.f);
        w0.z = fmaxf(p1.x + bj[2], 0.f); w0.w = fmaxf(p1.y + bj[3], 0.f);
        w1.x = fmaxf(p2.x + bj[4], 0.f); w1.y = fmaxf(p2.y + bj[5], 0.f);
        w1.z = fmaxf(p3.x + bj[6], 0.f); w1.w = fmaxf(p3.y + bj[7], 0.f);
        float* hrow = g_h + (size_t)row * DD + n_block;
        *(float4*)(hrow + tn)      = w0;
        *(float4*)(hrow + tn + 32) = w1;
        csum[0]+=w0.x; csum[1]+=w0.y; csum[2]+=w0.z; csum[3]+=w0.w;
        csum[4]+=w1.x; csum[5]+=w1.y; csum[6]+=w1.z; csum[7]+=w1.w;
    }
    __syncthreads();   // scol zero done before first stage sync; ensure all epilogue ready
    #pragma unroll
    for (int c = 0; c < 4; c++) {
        atomicAdd(&scol[tn + c], csum[c]);
        atomicAdd(&scol[tn + 32 + c], csum[4 + c]);
    }
    __syncthreads();
    if (tid < 128) atomicAdd(&g_colsum[n_block + tid], scol[tid]);
}

// ---------------- layer-2 reduction over edges (no agg2 materialization) ----
// grid (3750, 6), block 256
__global__ void reduce2_kernel(const int* __restrict__ varp, int use_var) {
    __shared__ float sh[128];
    int t = threadIdx.x;
    if (t < 128) sh[t] = 0.f;
    __syncthreads();
    int warp = t >> 5, lane = t & 31;
    int node = blockIdx.x * 8 + warp;
    int dl = lane * 4;
    int d = blockIdx.y * 128 + dl;
    int p0 = g_start[node], p1 = g_start[node + 1];
    float4 acc = make_float4(0.f, 0.f, 0.f, 0.f);
    int p = p0;
    for (; p + 4 <= p1; p += 4) {
        int s0 = g_sorted[p], s1 = g_sorted[p+1], s2 = g_sorted[p+2], s3 = g_sorted[p+3];
        float4 v0 = *(const float4*)(g_h + (size_t)s0 * DD + d);
        float4 v1 = *(const float4*)(g_h + (size_t)s1 * DD + d);
        float4 v2 = *(const float4*)(g_h + (size_t)s2 * DD + d);
        float4 v3 = *(const float4*)(g_h + (size_t)s3 * DD + d);
        acc.x += v0.x + v1.x + v2.x + v3.x;
        acc.y += v0.y + v1.y + v2.y + v3.y;
        acc.z += v0.z + v1.z + v2.z + v3.z;
        acc.w += v0.w + v1.w + v2.w + v3.w;
    }
    for (; p < p1; p++) {
        int s = g_sorted[p];
        float4 v = *(const float4*)(g_h + (size_t)s * DD + d);
        acc.x += v.x; acc.y += v.y; acc.z += v.z; acc.w += v.w;
    }
    float w = g_inv[node];
    atomicAdd(&sh[dl + 0], acc.x * w);
    atomicAdd(&sh[dl + 1], acc.y * w);
    atomicAdd(&sh[dl + 2], acc.z * w);
    atomicAdd(&sh[dl + 3], acc.w * w);
    if (use_var && node == *varp) {
        float4 o = make_float4(acc.x * w, acc.y * w, acc.z * w, acc.w * w);
        *(float4*)(g_agg2var + d) = o;
    }
    __syncthreads();
    if (t < 128) atomicAdd(&g_s2[blockIdx.y * 128 + t], sh[t]);
}

__global__ void rowvar_kernel(const int* __restrict__ varp) {
    int t = blockIdx.x * 256 + threadIdx.x;
    if (t < DD) g_rowvar[t] = g_h[(size_t)(*varp) * DD + t];
}

// ---------------- layer-2 matvecs:  out[j] = s*(a.Wl[j] + b.Wr[j]) + bias[j] -
__global__ void matvec2_kernel(const float* __restrict__ Wl, const float* __restrict__ bias,
                               const float* __restrict__ Wr, int mode) {
    const float *a, *b; float s; float* out;
    if (mode == 0)      { a = g_s2;      b = g_colsum; s = 1.0f / NN; out = g_emb1; }
    else if (mode == 1) { a = g_agg2var; b = g_rowvar; s = 1.0f;      out = g_emb2; }
    else                { a = g_s2;      b = g_colsum; s = 1.0f / NN; out = g_embt; }
    int j = blockIdx.x, t = threadIdx.x;   // 128 threads
    const float* wl = Wl + (size_t)j * DD;
    const float* wr = Wr + (size_t)j * DD;
    float p = 0.f;
    for (int k = t; k < DD; k += 128) p += a[k] * wl[k] + b[k] * wr[k];
    #pragma unroll
    for (int o = 16; o; o >>= 1) p += __shfl_xor_sync(0xffffffffu, p, o);
    __shared__ float sw[4];
    if ((t & 31) == 0) sw[t >> 5] = p;
    __syncthreads();
    if (t == 0) out[j] = (sw[0] + sw[1] + sw[2] + sw[3]) * s + bias[j];
}

// ---------------- head ----------------
__global__ void feats_kernel() {
    int t = blockIdx.x * 256 + threadIdx.x;
    if (t < DD) {
        float a = g_emb1[t], b = g_emb2[t];
        g_feats[t] = a; g_feats[DD + t] = b; g_feats[2 * DD + t] = a * b;
    }
}

__global__ void out_kernel(const float* __restrict__ linW, const float* __restrict__ linb,
                           const float* __restrict__ Wo, const float* __restrict__ ov,
                           const int* __restrict__ opp, float* __restrict__ dout) {
    int j = blockIdx.x, t = threadIdx.x;   // 256 threads
    const float* w = linW + (size_t)j * (3 * DD);
    float p = 0.f;
    for (int k = t; k < 3 * DD; k += 256) p += w[k] * g_feats[k];
    #pragma unroll
    for (int o = 16; o; o >>= 1) p += __shfl_xor_sync(0xffffffffu, p, o);
    __shared__ float sw[8];
    if ((t & 31) == 0) sw[t >> 5] = p;
    __syncthreads();
    if (t == 0) {
        float tot = 0.f;
        #pragma unroll
        for (int i = 0; i < 8; i++) tot += sw[i];
        int op = *opp - 1;
        float o = (tot + linb[j]) * Wo[(size_t)op * DD + j];
        float tg = g_embt[j] + ov[(size_t)op * DD + j];
        g_outv[j] = o; g_tgt[j] = tg;
        dout[3 + j] = o;
    }
}

__global__ void final_kernel(const float* __restrict__ labels, float* __restrict__ dout) {
    int t = threadIdx.x;   // 256
    float dd = 0.f, no = 0.f, nt = 0.f;
    for (int j = t; j < DD; j += 256) {
        float o = g_outv[j], g = g_tgt[j];
        dd += o * g; no += o * o; nt += g * g;
    }
    #pragma unroll
    for (int o = 16; o; o >>= 1) {
        dd += __shfl_xor_sync(0xffffffffu, dd, o);
        no += __shfl_xor_sync(0xffffffffu, no, o);
        nt += __shfl_xor_sync(0xffffffffu, nt, o);
    }
    __shared__ float s0[8], s1[8], s2[8];
    if ((t & 31) == 0) { s0[t >> 5] = dd; s1[t >> 5] = no; s2[t >> 5] = nt; }
    __syncthreads();
    if (t == 0) {
        float D_ = 0.f, NO = 0.f, NT = 0.f;
        #pragma unroll
        for (int i = 0; i < 8; i++) { D_ += s0[i]; NO += s1[i]; NT += s2[i]; }
        float n1 = fmaxf(sqrtf(NO), 1e-8f);
        float n2 = fmaxf(sqrtf(NT), 1e-8f);
        float score = D_ / (n1 * n2);
        float lab = labels[0];
        float loss = (score - lab) * (score - lab);
        dout[0] = loss; dout[1] = score; dout[2] = lab;
    }
}

// ---------------- launch ----------------
extern "C" void kernel_launch(void* const* d_in, const int* in_sizes, int n_in,
                              void* d_out, int out_size) {
    (void)in_sizes; (void)n_in; (void)out_size;
    const float* x1   = (const float*)d_in[0];
    const int*   ei1  = (const int*)d_in[1];
    const int*   varp = (const int*)d_in[2];
    const float* xt   = (const float*)d_in[3];
    const int*   eit  = (const int*)d_in[4];
    const int*   opp  = (const int*)d_in[5];
    const float* labels = (const float*)d_in[6];
    const float* Wl1 = (const float*)d_in[7];
    const float* bl1 = (const float*)d_in[8];
    const float* Wr1 = (const float*)d_in[9];
    const float* Wl2 = (const float*)d_in[10];
    const float* bl2 = (const float*)d_in[11];
    const float* Wr2 = (const float*)d_in[12];
    const float* linW = (const float*)d_in[13];
    const float* linb = (const float*)d_in[14];
    const float* Wo  = (const float*)d_in[15];
    const float* ov  = (const float*)d_in[16];
    float* dout = (float*)d_out;

    const int EB = (NE + 255) / 256;

    // ---- graph 1 ----
    zero_graph_kernel<<<118, 256>>>();
    count_kernel<<<EB, 256>>>(ei1);
    prefix_kernel<<<1, 1024>>>();
    place_kernel<<<EB, 256>>>(ei1);
    gather_agg_kernel<<<dim3(3750, 6), 256>>>(x1);
    gemm_relu_kernel<<<dim3(235, 6), 256>>>(x1, Wl1, bl1, Wr1);
    reduce2_kernel<<<dim3(3750, 6), 256>>>(varp, 1);
    rowvar_kernel<<<3, 256>>>(varp);
    matvec2_kernel<<<768, 128>>>(Wl2, bl2, Wr2, 0);   // emb1
    matvec2_kernel<<<768, 128>>>(Wl2, bl2, Wr2, 1);   // emb2

    // ---- graph t ----
    zero_graph_kernel<<<118, 256>>>();
    count_kernel<<<EB, 256>>>(eit);
    prefix_kernel<<<1, 1024>>>();
    place_kernel<<<EB, 256>>>(eit);
    gather_agg_kernel<<<dim3(3750, 6), 256>>>(xt);
    gemm_relu_kernel<<<dim3(235, 6), 256>>>(xt, Wl1, bl1, Wr1);
    reduce2_kernel<<<dim3(3750, 6), 256>>>(varp, 0);
    matvec2_kernel<<<768, 128>>>(Wl2, bl2, Wr2, 2);   // embt

    // ---- head ----
    feats_kernel<<<3, 256>>>();
    out_kernel<<<768, 256>>>(linW, linb, Wo, ov, opp, dout);
    final_kernel<<<1, 256>>>(labels, dout);
}

// round 3
// speedup vs baseline: 1.6658x; 1.6658x over previous
#include <cuda_runtime.h>
#include <cuda_bf16.h>
#include <cstdint>

#define NN 30000          // nodes per graph
#define DD 768            // feature dim
#define NE 480000         // edges per graph
#define K2 (2*DD)         // GEMM K = 1536

// ---------------- scratch (static device memory; no allocs) ----------------
__device__ unsigned short g_ah[(size_t)NN * DD];   // bf16 hi of agg (pre-scaled)
__device__ unsigned short g_al[(size_t)NN * DD];   // bf16 lo
__device__ unsigned short g_xh[(size_t)NN * DD];   // bf16 hi of x
__device__ unsigned short g_xl[(size_t)NN * DD];
__device__ unsigned short g_bh[(size_t)DD * K2];   // bf16 hi of [Wl1|Wr1], row j, col k
__device__ unsigned short g_bl[(size_t)DD * K2];
__device__ float g_h[(size_t)NN * DD];             // layer-1 output (fp32)
__device__ int   g_cnt[NN];
__device__ float g_inv[NN];
__device__ int   g_start[NN + 1];
__device__ int   g_cursor[NN];
__device__ int   g_sorted[NE];
__device__ float g_colsum[DD];
__device__ float g_s2[DD];
__device__ float g_agg2var[DD];
__device__ float g_rowvar[DD];
__device__ float g_emb1[DD], g_emb2[DD], g_embt[DD];
__device__ float g_feats[3 * DD];
__device__ float g_outv[DD], g_tgt[DD];

// ---------------- helpers ----------------
__device__ __forceinline__ unsigned short bfh(float v) {
    __nv_bfloat16 h = __float2bfloat16(v);
    return *reinterpret_cast<unsigned short*>(&h);
}
__device__ __forceinline__ float bf2f(unsigned short u) {
    __nv_bfloat16 h = *reinterpret_cast<__nv_bfloat16*>(&u);
    return __bfloat162float(h);
}

#define MMA_BF16(acc, a0, a1, a2, a3, b0, b1) \
    asm volatile("mma.sync.aligned.m16n8k16.row.col.f32.bf16.bf16.f32 " \
        "{%0,%1,%2,%3}, {%4,%5,%6,%7}, {%8,%9}, {%0,%1,%2,%3};" \
        : "+f"((acc)[0]), "+f"((acc)[1]), "+f"((acc)[2]), "+f"((acc)[3]) \
        : "r"(a0), "r"(a1), "r"(a2), "r"(a3), "r"(b0), "r"(b1))

// ---------------- graph prep ----------------
__global__ void zero_graph_kernel() {
    int t = blockIdx.x * 256 + threadIdx.x;
    if (t < NN) g_cnt[t] = 0;
    if (t < DD) { g_colsum[t] = 0.f; g_s2[t] = 0.f; g_agg2var[t] = 0.f; }
}

__global__ void count_kernel(const int* __restrict__ ei) {
    int e = blockIdx.x * 256 + threadIdx.x;
    if (e < NE) atomicAdd(&g_cnt[ei[NE + e]], 1);
}

__global__ void prefix_kernel() {   // 1 block, 1024 threads
    __shared__ int sh[1024];
    __shared__ int carry;
    int tid = threadIdx.x;
    if (tid == 0) carry = 0;
    __syncthreads();
    for (int base = 0; base < NN; base += 1024) {
        int i = base + tid;
        int v = (i < NN) ? g_cnt[i] : 0;
        int xv = v;
        #pragma unroll
        for (int off = 1; off < 1024; off <<= 1) {
            sh[tid] = xv; __syncthreads();
            if (tid >= off) xv += sh[tid - off];
            __syncthreads();
        }
        int incl = xv + carry;
        if (i < NN) {
            int excl = incl - v;
            g_start[i] = excl;
            g_cursor[i] = excl;
            g_inv[i] = 1.0f / (float)max(v, 1);
        }
        __syncthreads();
        if (tid == 1023) carry = incl;
        __syncthreads();
    }
    if (tid == 0) g_start[NN] = carry;
}

__global__ void place_kernel(const int* __restrict__ ei) {
    int e = blockIdx.x * 256 + threadIdx.x;
    if (e < NE) {
        int s = ei[e], t = ei[NE + e];
        int pos = atomicAdd(&g_cursor[t], 1);
        g_sorted[pos] = s;
    }
}

// ---------------- weight / x splits ----------------
__global__ void convert_b_kernel(const float* __restrict__ Wl, const float* __restrict__ Wr) {
    int i = blockIdx.x * 256 + threadIdx.x;
    if (i < DD * K2) {
        int j = i / K2, k = i % K2;
        float v = (k < DD) ? Wl[(size_t)j * DD + k] : Wr[(size_t)j * DD + (k - DD)];
        unsigned short hi = bfh(v);
        g_bh[i] = hi;
        g_bl[i] = bfh(v - bf2f(hi));
    }
}

__global__ void convert_x_kernel(const float* __restrict__ x) {
    size_t i = ((size_t)blockIdx.x * 256 + threadIdx.x) * 8;
    if (i >= (size_t)NN * DD) return;
    float4 v0 = *(const float4*)(x + i);
    float4 v1 = *(const float4*)(x + i + 4);
    float vv[8] = {v0.x, v0.y, v0.z, v0.w, v1.x, v1.y, v1.z, v1.w};
    unsigned short h[8], l[8];
    #pragma unroll
    for (int j = 0; j < 8; j++) {
        h[j] = bfh(vv[j]);
        l[j] = bfh(vv[j] - bf2f(h[j]));
    }
    uint4 H, L;
    H.x = h[0] | ((uint32_t)h[1] << 16); H.y = h[2] | ((uint32_t)h[3] << 16);
    H.z = h[4] | ((uint32_t)h[5] << 16); H.w = h[6] | ((uint32_t)h[7] << 16);
    L.x = l[0] | ((uint32_t)l[1] << 16); L.y = l[2] | ((uint32_t)l[3] << 16);
    L.z = l[4] | ((uint32_t)l[5] << 16); L.w = l[6] | ((uint32_t)l[7] << 16);
    *(uint4*)(g_xh + i) = H;
    *(uint4*)(g_xl + i) = L;
}

// ---------------- layer-1 aggregation: gather by dst segment -> bf16 hi/lo --
__global__ void gather_agg_kernel(const float* __restrict__ x) {
    int warp = threadIdx.x >> 5, lane = threadIdx.x & 31;
    int node = blockIdx.x * 8 + warp;
    int d = blockIdx.y * 128 + lane * 4;
    int p0 = g_start[node], p1 = g_start[node + 1];
    float4 acc = make_float4(0.f, 0.f, 0.f, 0.f);
    int p = p0;
    for (; p + 4 <= p1; p += 4) {
        int s0 = g_sorted[p], s1 = g_sorted[p+1], s2 = g_sorted[p+2], s3 = g_sorted[p+3];
        float4 v0 = *(const float4*)(x + (size_t)s0 * DD + d);
        float4 v1 = *(const float4*)(x + (size_t)s1 * DD + d);
        float4 v2 = *(const float4*)(x + (size_t)s2 * DD + d);
        float4 v3 = *(const float4*)(x + (size_t)s3 * DD + d);
        acc.x += v0.x + v1.x + v2.x + v3.x;
        acc.y += v0.y + v1.y + v2.y + v3.y;
        acc.z += v0.z + v1.z + v2.z + v3.z;
        acc.w += v0.w + v1.w + v2.w + v3.w;
    }
    for (; p < p1; p++) {
        int s = g_sorted[p];
        float4 v = *(const float4*)(x + (size_t)s * DD + d);
        acc.x += v.x; acc.y += v.y; acc.z += v.z; acc.w += v.w;
    }
    float inv = g_inv[node];
    acc.x *= inv; acc.y *= inv; acc.z *= inv; acc.w *= inv;
    ushort4 hv, lv;
    hv.x = bfh(acc.x); lv.x = bfh(acc.x - bf2f(hv.x));
    hv.y = bfh(acc.y); lv.y = bfh(acc.y - bf2f(hv.y));
    hv.z = bfh(acc.z); lv.z = bfh(acc.z - bf2f(hv.z));
    hv.w = bfh(acc.w); lv.w = bfh(acc.w - bf2f(hv.w));
    *(ushort4*)(g_ah + (size_t)node * DD + d) = hv;
    *(ushort4*)(g_al + (size_t)node * DD + d) = lv;
}

// ---------------- bf16 3-split mma.sync GEMM:  h = relu([agg|x] @ B^T + b) --
// grid (235, 6), 256 thr. CTA tile 128x128, K chunks of 32.
// Warps: wm in {0,1} x 64 rows, wn in {0..3} x 32 cols. Warp tile 64x32.
__global__ __launch_bounds__(256, 2)
void gemm_mma_kernel(const float* __restrict__ bias) {
    __shared__ __align__(16) unsigned short sAh[128 * 40];
    __shared__ __align__(16) unsigned short sAl[128 * 40];
    __shared__ __align__(16) unsigned short sBh[128 * 40];
    __shared__ __align__(16) unsigned short sBl[128 * 40];
    __shared__ float scol[128];

    const int tid = threadIdx.x;
    const int m_block = blockIdx.x * 128;
    const int n_block = blockIdx.y * 128;
    if (tid < 128) scol[tid] = 0.f;

    const int warp = tid >> 5, lane = tid & 31;
    const int wm = warp & 1, wn = warp >> 1;
    const int g = lane >> 2, tg = lane & 3;

    float acc[4][4][4];
    #pragma unroll
    for (int i = 0; i < 4; i++)
        #pragma unroll
        for (int j = 0; j < 4; j++)
            #pragma unroll
            for (int q = 0; q < 4; q++) acc[i][j][q] = 0.f;

    for (int c = 0; c < 48; c++) {
        const int kc = c * 32;
        const unsigned short* pah;
        const unsigned short* pal;
        int colb;
        if (c < 24) { pah = g_ah; pal = g_al; colb = kc; }
        else        { pah = g_xh; pal = g_xl; colb = kc - DD; }
        __syncthreads();
        #pragma unroll
        for (int i2 = 0; i2 < 2; i2++) {
            int idx = i2 * 256 + tid;
            int row = idx >> 2, q = idx & 3;
            int grow = m_block + row;
            uint4 vh = make_uint4(0, 0, 0, 0), vl = make_uint4(0, 0, 0, 0);
            if (grow < NN) {
                vh = *(const uint4*)(pah + (size_t)grow * DD + colb + q * 8);
                vl = *(const uint4*)(pal + (size_t)grow * DD + colb + q * 8);
            }
            *(uint4*)((char*)sAh + row * 80 + q * 16) = vh;
            *(uint4*)((char*)sAl + row * 80 + q * 16) = vl;
            size_t gb = (size_t)(n_block + row) * K2 + kc + q * 8;
            *(uint4*)((char*)sBh + row * 80 + q * 16) = *(const uint4*)(g_bh + gb);
            *(uint4*)((char*)sBl + row * 80 + q * 16) = *(const uint4*)(g_bl + gb);
        }
        __syncthreads();
        #pragma unroll
        for (int ks = 0; ks < 2; ks++) {
            const int kb = (ks * 16 + tg * 2) * 2;   // byte offset of this thread's k pair
            uint32_t bh[4][2], bl[4][2];
            #pragma unroll
            for (int j = 0; j < 4; j++) {
                int n = wn * 32 + j * 8 + g;
                const char* ph = (const char*)sBh + n * 80 + kb;
                const char* pl = (const char*)sBl + n * 80 + kb;
                bh[j][0] = *(const uint32_t*)ph;  bh[j][1] = *(const uint32_t*)(ph + 16);
                bl[j][0] = *(const uint32_t*)pl;  bl[j][1] = *(const uint32_t*)(pl + 16);
            }
            #pragma unroll
            for (int i = 0; i < 4; i++) {
                int m = wm * 64 + i * 16 + g;
                const char* ph = (const char*)sAh + m * 80 + kb;
                const char* pl = (const char*)sAl + m * 80 + kb;
                uint32_t ah0 = *(const uint32_t*)ph;
                uint32_t ah1 = *(const uint32_t*)(ph + 640);
                uint32_t ah2 = *(const uint32_t*)(ph + 16);
                uint32_t ah3 = *(const uint32_t*)(ph + 656);
                uint32_t al0 = *(const uint32_t*)pl;
                uint32_t al1 = *(const uint32_t*)(pl + 640);
                uint32_t al2 = *(const uint32_t*)(pl + 16);
                uint32_t al3 = *(const uint32_t*)(pl + 656);
                #pragma unroll
                for (int j = 0; j < 4; j++) {
                    MMA_BF16(acc[i][j], ah0, ah1, ah2, ah3, bh[j][0], bh[j][1]);
                    MMA_BF16(acc[i][j], al0, al1, al2, al3, bh[j][0], bh[j][1]);
                    MMA_BF16(acc[i][j], ah0, ah1, ah2, ah3, bl[j][0], bl[j][1]);
                }
            }
        }
    }

    // epilogue: bias + relu, store h (float2), fused column sums
    #pragma unroll
    for (int j = 0; j < 4; j++) {
        int ncol = wn * 32 + j * 8 + 2 * tg;
        int n0 = n_block + ncol;
        float b0 = bias[n0], b1 = bias[n0 + 1];
        float cs0 = 0.f, cs1 = 0.f;
        #pragma unroll
        for (int i = 0; i < 4; i++) {
            int r0 = m_block + wm * 64 + i * 16 + g;
            int r1 = r0 + 8;
            if (r0 < NN) {
                float v0 = fmaxf(acc[i][j][0] + b0, 0.f);
                float v1 = fmaxf(acc[i][j][1] + b1, 0.f);
                *(float2*)(g_h + (size_t)r0 * DD + n0) = make_float2(v0, v1);
                cs0 += v0; cs1 += v1;
            }
            if (r1 < NN) {
                float v2 = fmaxf(acc[i][j][2] + b0, 0.f);
                float v3 = fmaxf(acc[i][j][3] + b1, 0.f);
                *(float2*)(g_h + (size_t)r1 * DD + n0) = make_float2(v2, v3);
                cs0 += v2; cs1 += v3;
            }
        }
        atomicAdd(&scol[ncol], cs0);
        atomicAdd(&scol[ncol + 1], cs1);
    }
    __syncthreads();
    if (tid < 128) atomicAdd(&g_colsum[n_block + tid], scol[tid]);
}

// ---------------- layer-2 reduction over edges (no agg2 materialization) ----
__global__ void reduce2_kernel(const int* __restrict__ varp, int use_var) {
    __shared__ float sh[128];
    int t = threadIdx.x;
    if (t < 128) sh[t] = 0.f;
    __syncthreads();
    int warp = t >> 5, lane = t & 31;
    int node = blockIdx.x * 8 + warp;
    int dl = lane * 4;
    int d = blockIdx.y * 128 + dl;
    int p0 = g_start[node], p1 = g_start[node + 1];
    float4 acc = make_float4(0.f, 0.f, 0.f, 0.f);
    int p = p0;
    for (; p + 4 <= p1; p += 4) {
        int s0 = g_sorted[p], s1 = g_sorted[p+1], s2 = g_sorted[p+2], s3 = g_sorted[p+3];
        float4 v0 = *(const float4*)(g_h + (size_t)s0 * DD + d);
        float4 v1 = *(const float4*)(g_h + (size_t)s1 * DD + d);
        float4 v2 = *(const float4*)(g_h + (size_t)s2 * DD + d);
        float4 v3 = *(const float4*)(g_h + (size_t)s3 * DD + d);
        acc.x += v0.x + v1.x + v2.x + v3.x;
        acc.y += v0.y + v1.y + v2.y + v3.y;
        acc.z += v0.z + v1.z + v2.z + v3.z;
        acc.w += v0.w + v1.w + v2.w + v3.w;
    }
    for (; p < p1; p++) {
        int s = g_sorted[p];
        float4 v = *(const float4*)(g_h + (size_t)s * DD + d);
        acc.x += v.x; acc.y += v.y; acc.z += v.z; acc.w += v.w;
    }
    float wgt = g_inv[node];
    atomicAdd(&sh[dl + 0], acc.x * wgt);
    atomicAdd(&sh[dl + 1], acc.y * wgt);
    atomicAdd(&sh[dl + 2], acc.z * wgt);
    atomicAdd(&sh[dl + 3], acc.w * wgt);
    if (use_var && node == *varp) {
        float4 o = make_float4(acc.x * wgt, acc.y * wgt, acc.z * wgt, acc.w * wgt);
        *(float4*)(g_agg2var + d) = o;
    }
    __syncthreads();
    if (t < 128) atomicAdd(&g_s2[blockIdx.y * 128 + t], sh[t]);
}

__global__ void rowvar_kernel(const int* __restrict__ varp) {
    int t = blockIdx.x * 256 + threadIdx.x;
    if (t < DD) g_rowvar[t] = g_h[(size_t)(*varp) * DD + t];
}

// ---------------- layer-2 matvecs ----------------
__global__ void matvec2_kernel(const float* __restrict__ Wl, const float* __restrict__ bias,
                               const float* __restrict__ Wr, int mode) {
    const float *a, *b; float s; float* out;
    if (mode == 0)      { a = g_s2;      b = g_colsum; s = 1.0f / NN; out = g_emb1; }
    else if (mode == 1) { a = g_agg2var; b = g_rowvar; s = 1.0f;      out = g_emb2; }
    else                { a = g_s2;      b = g_colsum; s = 1.0f / NN; out = g_embt; }
    int j = blockIdx.x, t = threadIdx.x;   // 128 threads
    const float* wl = Wl + (size_t)j * DD;
    const float* wr = Wr + (size_t)j * DD;
    float p = 0.f;
    for (int k = t; k < DD; k += 128) p += a[k] * wl[k] + b[k] * wr[k];
    #pragma unroll
    for (int o = 16; o; o >>= 1) p += __shfl_xor_sync(0xffffffffu, p, o);
    __shared__ float sw[4];
    if ((t & 31) == 0) sw[t >> 5] = p;
    __syncthreads();
    if (t == 0) out[j] = (sw[0] + sw[1] + sw[2] + sw[3]) * s + bias[j];
}

// ---------------- head ----------------
__global__ void feats_kernel() {
    int t = blockIdx.x * 256 + threadIdx.x;
    if (t < DD) {
        float a = g_emb1[t], b = g_emb2[t];
        g_feats[t] = a; g_feats[DD + t] = b; g_feats[2 * DD + t] = a * b;
    }
}

__global__ void out_kernel(const float* __restrict__ linW, const float* __restrict__ linb,
                           const float* __restrict__ Wo, const float* __restrict__ ov,
                           const int* __restrict__ opp, float* __restrict__ dout) {
    int j = blockIdx.x, t = threadIdx.x;   // 256 threads
    const float* w = linW + (size_t)j * (3 * DD);
    float p = 0.f;
    for (int k = t; k < 3 * DD; k += 256) p += w[k] * g_feats[k];
    #pragma unroll
    for (int o = 16; o; o >>= 1) p += __shfl_xor_sync(0xffffffffu, p, o);
    __shared__ float sw[8];
    if ((t & 31) == 0) sw[t >> 5] = p;
    __syncthreads();
    if (t == 0) {
        float tot = 0.f;
        #pragma unroll
        for (int i = 0; i < 8; i++) tot += sw[i];
        int op = *opp - 1;
        float o = (tot + linb[j]) * Wo[(size_t)op * DD + j];
        float tg = g_embt[j] + ov[(size_t)op * DD + j];
        g_outv[j] = o; g_tgt[j] = tg;
        dout[3 + j] = o;
    }
}

__global__ void final_kernel(const float* __restrict__ labels, float* __restrict__ dout) {
    int t = threadIdx.x;   // 256
    float dd = 0.f, no = 0.f, nt = 0.f;
    for (int j = t; j < DD; j += 256) {
        float o = g_outv[j], g = g_tgt[j];
        dd += o * g; no += o * o; nt += g * g;
    }
    #pragma unroll
    for (int o = 16; o; o >>= 1) {
        dd += __shfl_xor_sync(0xffffffffu, dd, o);
        no += __shfl_xor_sync(0xffffffffu, no, o);
        nt += __shfl_xor_sync(0xffffffffu, nt, o);
    }
    __shared__ float s0[8], s1[8], s2[8];
    if ((t & 31) == 0) { s0[t >> 5] = dd; s1[t >> 5] = no; s2[t >> 5] = nt; }
    __syncthreads();
    if (t == 0) {
        float D_ = 0.f, NO = 0.f, NT = 0.f;
        #pragma unroll
        for (int i = 0; i < 8; i++) { D_ += s0[i]; NO += s1[i]; NT += s2[i]; }
        float n1 = fmaxf(sqrtf(NO), 1e-8f);
        float n2 = fmaxf(sqrtf(NT), 1e-8f);
        float score = D_ / (n1 * n2);
        float lab = labels[0];
        float loss = (score - lab) * (score - lab);
        dout[0] = loss; dout[1] = score; dout[2] = lab;
    }
}

// ---------------- launch ----------------
extern "C" void kernel_launch(void* const* d_in, const int* in_sizes, int n_in,
                              void* d_out, int out_size) {
    (void)in_sizes; (void)n_in; (void)out_size;
    const float* x1   = (const float*)d_in[0];
    const int*   ei1  = (const int*)d_in[1];
    const int*   varp = (const int*)d_in[2];
    const float* xt   = (const float*)d_in[3];
    const int*   eit  = (const int*)d_in[4];
    const int*   opp  = (const int*)d_in[5];
    const float* labels = (const float*)d_in[6];
    const float* Wl1 = (const float*)d_in[7];
    const float* bl1 = (const float*)d_in[8];
    const float* Wr1 = (const float*)d_in[9];
    const float* Wl2 = (const float*)d_in[10];
    const float* bl2 = (const float*)d_in[11];
    const float* Wr2 = (const float*)d_in[12];
    const float* linW = (const float*)d_in[13];
    const float* linb = (const float*)d_in[14];
    const float* Wo  = (const float*)d_in[15];
    const float* ov  = (const float*)d_in[16];
    float* dout = (float*)d_out;

    const int EB = (NE + 255) / 256;
    const int XB = ((NN * DD / 8) + 255) / 256;

    convert_b_kernel<<<(DD * K2 + 255) / 256, 256>>>(Wl1, Wr1);

    // ---- graph 1 ----
    zero_graph_kernel<<<118, 256>>>();
    count_kernel<<<EB, 256>>>(ei1);
    prefix_kernel<<<1, 1024>>>();
    place_kernel<<<EB, 256>>>(ei1);
    convert_x_kernel<<<XB, 256>>>(x1);
    gather_agg_kernel<<<dim3(3750, 6), 256>>>(x1);
    gemm_mma_kernel<<<dim3(235, 6), 256>>>(bl1);
    reduce2_kernel<<<dim3(3750, 6), 256>>>(varp, 1);
    rowvar_kernel<<<3, 256>>>(varp);
    matvec2_kernel<<<768, 128>>>(Wl2, bl2, Wr2, 0);   // emb1
    matvec2_kernel<<<768, 128>>>(Wl2, bl2, Wr2, 1);   // emb2

    // ---- graph t ----
    zero_graph_kernel<<<118, 256>>>();
    count_kernel<<<EB, 256>>>(eit);
    prefix_kernel<<<1, 1024>>>();
    place_kernel<<<EB, 256>>>(eit);
    convert_x_kernel<<<XB, 256>>>(xt);
    gather_agg_kernel<<<dim3(3750, 6), 256>>>(xt);
    gemm_mma_kernel<<<dim3(235, 6), 256>>>(bl1);
    reduce2_kernel<<<dim3(3750, 6), 256>>>(varp, 0);
    matvec2_kernel<<<768, 128>>>(Wl2, bl2, Wr2, 2);   // embt

    // ---- head ----
    feats_kernel<<<3, 256>>>();
    out_kernel<<<768, 256>>>(linW, linb, Wo, ov, opp, dout);
    final_kernel<<<1, 256>>>(labels, dout);
}

// round 4
// speedup vs baseline: 1.7541x; 1.0530x over previous
#include <cuda_runtime.h>
#include <cuda_bf16.h>
#include <cstdint>

#define NN 30000          // nodes per graph
#define DD 768            // feature dim
#define NE 480000         // edges per graph
#define K2 (2*DD)         // GEMM K = 1536

// ---------------- scratch (static device memory; no allocs) ----------------
__device__ unsigned short g_ah[(size_t)NN * DD];   // bf16 hi of agg (pre-scaled)
__device__ unsigned short g_al[(size_t)NN * DD];   // bf16 lo
__device__ unsigned short g_xh[(size_t)NN * DD];   // bf16 hi of x
__device__ unsigned short g_xl[(size_t)NN * DD];
__device__ unsigned short g_bh[(size_t)DD * K2];   // bf16 hi of [Wl1|Wr1], row j, col k
__device__ unsigned short g_bl[(size_t)DD * K2];
__device__ float g_h[(size_t)NN * DD];             // layer-1 output (graph1 only)
__device__ int   g_cnt[NN];
__device__ float g_inv[NN];
__device__ float g_cw[NN];                         // c_j = sum over out-edges of inv[dst]
__device__ int   g_start[NN + 1];
__device__ int   g_cursor[NN];
__device__ int   g_sorted[NE];
__device__ float g_colsum[DD];                     // sum over nodes of h
__device__ float g_s2[DD];                         // sum_j c_j h_j = N*mean(agg2)
__device__ float g_agg2var[DD];
__device__ float g_rowvar[DD];
__device__ float g_emb1[DD], g_emb2[DD], g_embt[DD];
__device__ float g_feats[3 * DD];
__device__ float g_outv[DD], g_tgt[DD];

// ---------------- helpers ----------------
__device__ __forceinline__ unsigned short bfh(float v) {
    __nv_bfloat16 h = __float2bfloat16(v);
    return *reinterpret_cast<unsigned short*>(&h);
}
__device__ __forceinline__ float bf2f(unsigned short u) {
    __nv_bfloat16 h = *reinterpret_cast<__nv_bfloat16*>(&u);
    return __bfloat162float(h);
}
__device__ __forceinline__ void cpa16(uint32_t d, const void* s, int sz) {
    asm volatile("cp.async.cg.shared.global [%0], [%1], 16, %2;"
                 :: "r"(d), "l"(s), "r"(sz) : "memory");
}
#define CP_COMMIT() asm volatile("cp.async.commit_group;" ::: "memory")
#define CP_WAIT1()  asm volatile("cp.async.wait_group 1;" ::: "memory")

#define MMA_BF16(acc, a0, a1, a2, a3, b0, b1) \
    asm volatile("mma.sync.aligned.m16n8k16.row.col.f32.bf16.bf16.f32 " \
        "{%0,%1,%2,%3}, {%4,%5,%6,%7}, {%8,%9}, {%0,%1,%2,%3};" \
        : "+f"((acc)[0]), "+f"((acc)[1]), "+f"((acc)[2]), "+f"((acc)[3]) \
        : "r"(a0), "r"(a1), "r"(a2), "r"(a3), "r"(b0), "r"(b1))

// ---------------- graph prep ----------------
__global__ void zero_graph_kernel() {
    int t = blockIdx.x * 256 + threadIdx.x;
    if (t < NN) { g_cnt[t] = 0; g_cw[t] = 0.f; }
    if (t < DD) { g_colsum[t] = 0.f; g_s2[t] = 0.f; g_agg2var[t] = 0.f; }
}

__global__ void count_kernel(const int* __restrict__ ei) {
    int e = blockIdx.x * 256 + threadIdx.x;
    if (e < NE) atomicAdd(&g_cnt[ei[NE + e]], 1);
}

// two-pass warp-shuffle scan, 1024 threads, 30 elems/thread
__global__ void prefix_kernel() {
    const int PT = 30;
    int tid = threadIdx.x;
    int base = tid * PT;
    int s = 0;
    #pragma unroll
    for (int i = 0; i < PT; i++) {
        int idx = base + i;
        s += (idx < NN) ? g_cnt[idx] : 0;
    }
    int lane = tid & 31, w = tid >> 5;
    int incl = s;
    #pragma unroll
    for (int off = 1; off < 32; off <<= 1) {
        int v = __shfl_up_sync(0xffffffffu, incl, off);
        if (lane >= off) incl += v;
    }
    __shared__ int wsum[32];
    if (lane == 31) wsum[w] = incl;
    __syncthreads();
    if (w == 0) {
        int v = wsum[lane];
        int iv = v;
        #pragma unroll
        for (int off = 1; off < 32; off <<= 1) {
            int u = __shfl_up_sync(0xffffffffu, iv, off);
            if (lane >= off) iv += u;
        }
        wsum[lane] = iv - v;   // exclusive
    }
    __syncthreads();
    int run = wsum[w] + incl - s;   // block-exclusive offset for this thread
    #pragma unroll
    for (int i = 0; i < PT; i++) {
        int idx = base + i;
        if (idx < NN) {
            int v = g_cnt[idx];
            g_start[idx] = run;
            g_cursor[idx] = run;
            g_inv[idx] = 1.0f / (float)max(v, 1);
            run += v;
        }
    }
    if (tid == 1023) g_start[NN] = run;
}

// placement + c-weight scatter fused
__global__ void place_kernel(const int* __restrict__ ei) {
    int e = blockIdx.x * 256 + threadIdx.x;
    if (e < NE) {
        int s = ei[e], t = ei[NE + e];
        int pos = atomicAdd(&g_cursor[t], 1);
        g_sorted[pos] = s;
        atomicAdd(&g_cw[s], g_inv[t]);
    }
}

// ---------------- weight / x splits ----------------
__global__ void convert_b_kernel(const float* __restrict__ Wl, const float* __restrict__ Wr) {
    int i = blockIdx.x * 256 + threadIdx.x;
    if (i < DD * K2) {
        int j = i / K2, k = i % K2;
        float v = (k < DD) ? Wl[(size_t)j * DD + k] : Wr[(size_t)j * DD + (k - DD)];
        unsigned short hi = bfh(v);
        g_bh[i] = hi;
        g_bl[i] = bfh(v - bf2f(hi));
    }
}

__global__ void convert_x_kernel(const float* __restrict__ x) {
    size_t i = ((size_t)blockIdx.x * 256 + threadIdx.x) * 8;
    if (i >= (size_t)NN * DD) return;
    float4 v0 = *(const float4*)(x + i);
    float4 v1 = *(const float4*)(x + i + 4);
    float vv[8] = {v0.x, v0.y, v0.z, v0.w, v1.x, v1.y, v1.z, v1.w};
    unsigned short h[8], l[8];
    #pragma unroll
    for (int j = 0; j < 8; j++) {
        h[j] = bfh(vv[j]);
        l[j] = bfh(vv[j] - bf2f(h[j]));
    }
    uint4 H, L;
    H.x = h[0] | ((uint32_t)h[1] << 16); H.y = h[2] | ((uint32_t)h[3] << 16);
    H.z = h[4] | ((uint32_t)h[5] << 16); H.w = h[6] | ((uint32_t)h[7] << 16);
    L.x = l[0] | ((uint32_t)l[1] << 16); L.y = l[2] | ((uint32_t)l[3] << 16);
    L.z = l[4] | ((uint32_t)l[5] << 16); L.w = l[6] | ((uint32_t)l[7] << 16);
    *(uint4*)(g_xh + i) = H;
    *(uint4*)(g_xl + i) = L;
}

// ---------------- layer-1 aggregation: gather by dst segment -> bf16 hi/lo --
__global__ void gather_agg_kernel(const float* __restrict__ x) {
    int warp = threadIdx.x >> 5, lane = threadIdx.x & 31;
    int node = blockIdx.x * 8 + warp;
    int d = blockIdx.y * 128 + lane * 4;
    int p0 = g_start[node], p1 = g_start[node + 1];
    float4 acc = make_float4(0.f, 0.f, 0.f, 0.f);
    int p = p0;
    for (; p + 4 <= p1; p += 4) {
        int s0 = g_sorted[p], s1 = g_sorted[p+1], s2 = g_sorted[p+2], s3 = g_sorted[p+3];
        float4 v0 = *(const float4*)(x + (size_t)s0 * DD + d);
        float4 v1 = *(const float4*)(x + (size_t)s1 * DD + d);
        float4 v2 = *(const float4*)(x + (size_t)s2 * DD + d);
        float4 v3 = *(const float4*)(x + (size_t)s3 * DD + d);
        acc.x += v0.x + v1.x + v2.x + v3.x;
        acc.y += v0.y + v1.y + v2.y + v3.y;
        acc.z += v0.z + v1.z + v2.z + v3.z;
        acc.w += v0.w + v1.w + v2.w + v3.w;
    }
    for (; p < p1; p++) {
        int s = g_sorted[p];
        float4 v = *(const float4*)(x + (size_t)s * DD + d);
        acc.x += v.x; acc.y += v.y; acc.z += v.z; acc.w += v.w;
    }
    float inv = g_inv[node];
    acc.x *= inv; acc.y *= inv; acc.z *= inv; acc.w *= inv;
    ushort4 hv, lv;
    hv.x = bfh(acc.x); lv.x = bfh(acc.x - bf2f(hv.x));
    hv.y = bfh(acc.y); lv.y = bfh(acc.y - bf2f(hv.y));
    hv.z = bfh(acc.z); lv.z = bfh(acc.z - bf2f(hv.z));
    hv.w = bfh(acc.w); lv.w = bfh(acc.w - bf2f(hv.w));
    *(ushort4*)(g_ah + (size_t)node * DD + d) = hv;
    *(ushort4*)(g_al + (size_t)node * DD + d) = lv;
}

// ---------------- bf16 3-split mma.sync GEMM, cp.async 3-stage pipeline -----
// grid (6 n-blocks, 235 m-blocks), 256 thr. CTA tile 128x128, K chunks of 32.
// Stage layout (40960 B): Ah @0, Al @10240, Bh @20480, Bl @30720; rows 80 B.
#define STG 40960
#define SMEM_GEMM (3 * STG)

__global__ __launch_bounds__(256, 1)
void gemm_mma_kernel(const float* __restrict__ bias, int store_h) {
    extern __shared__ __align__(16) char dsm[];
    __shared__ float scol[128], scol2[128];

    const int tid = threadIdx.x;
    const int n_block = blockIdx.x * 128;
    const int m_block = blockIdx.y * 128;
    if (tid < 128) { scol[tid] = 0.f; scol2[tid] = 0.f; }

    const uint32_t sbase = (uint32_t)__cvta_generic_to_shared(dsm);

    const int warp = tid >> 5, lane = tid & 31;
    const int wm = warp & 1, wn = warp >> 1;
    const int g = lane >> 2, tg = lane & 3;

    float acc[4][4][4];
    #pragma unroll
    for (int i = 0; i < 4; i++)
        #pragma unroll
        for (int j = 0; j < 4; j++)
            #pragma unroll
            for (int q = 0; q < 4; q++) acc[i][j][q] = 0.f;

    auto issue_chunk = [&](int c) {
        const int buf = c % 3;
        const uint32_t st = sbase + buf * STG;
        const int kc = c * 32;
        const unsigned short *pah, *pal;
        int colb;
        if (c < 24) { pah = g_ah; pal = g_al; colb = kc; }
        else        { pah = g_xh; pal = g_xl; colb = kc - DD; }
        #pragma unroll
        for (int i2 = 0; i2 < 2; i2++) {
            int idx = i2 * 256 + tid;
            int row = idx >> 2, q = idx & 3;
            int grow = m_block + row;
            uint32_t d0 = st + row * 80 + q * 16;
            size_t ga = (size_t)grow * DD + colb + q * 8;
            int sz = (grow < NN) ? 16 : 0;
            cpa16(d0,         pah + ga, sz);
            cpa16(d0 + 10240, pal + ga, sz);
            size_t gb = (size_t)(n_block + row) * K2 + kc + q * 8;
            cpa16(d0 + 20480, g_bh + gb, 16);
            cpa16(d0 + 30720, g_bl + gb, 16);
        }
        CP_COMMIT();
    };

    issue_chunk(0);
    issue_chunk(1);

    for (int c = 0; c < 48; c++) {
        CP_WAIT1();
        __syncthreads();
        if (c + 2 < 48) issue_chunk(c + 2);
        else CP_COMMIT();   // keep group counts consistent

        const char* bufp = dsm + (c % 3) * STG;
        const char* sAh = bufp;
        const char* sAl = bufp + 10240;
        const char* sBh = bufp + 20480;
        const char* sBl = bufp + 30720;

        #pragma unroll
        for (int ks = 0; ks < 2; ks++) {
            const int kb = (ks * 16 + tg * 2) * 2;   // byte offset of this thread's k pair
            uint32_t bh[4][2], bl[4][2];
            #pragma unroll
            for (int j = 0; j < 4; j++) {
                int n = wn * 32 + j * 8 + g;
                const char* ph = sBh + n * 80 + kb;
                const char* pl = sBl + n * 80 + kb;
                bh[j][0] = *(const uint32_t*)ph;  bh[j][1] = *(const uint32_t*)(ph + 16);
                bl[j][0] = *(const uint32_t*)pl;  bl[j][1] = *(const uint32_t*)(pl + 16);
            }
            #pragma unroll
            for (int i = 0; i < 4; i++) {
                int m = wm * 64 + i * 16 + g;
                const char* ph = sAh + m * 80 + kb;
                const char* pl = sAl + m * 80 + kb;
                uint32_t ah0 = *(const uint32_t*)ph;
                uint32_t ah1 = *(const uint32_t*)(ph + 640);
                uint32_t ah2 = *(const uint32_t*)(ph + 16);
                uint32_t ah3 = *(const uint32_t*)(ph + 656);
                uint32_t al0 = *(const uint32_t*)pl;
                uint32_t al1 = *(const uint32_t*)(pl + 640);
                uint32_t al2 = *(const uint32_t*)(pl + 16);
                uint32_t al3 = *(const uint32_t*)(pl + 656);
                #pragma unroll
                for (int j = 0; j < 4; j++) {
                    MMA_BF16(acc[i][j], ah0, ah1, ah2, ah3, bh[j][0], bh[j][1]);
                    MMA_BF16(acc[i][j], al0, al1, al2, al3, bh[j][0], bh[j][1]);
                    MMA_BF16(acc[i][j], ah0, ah1, ah2, ah3, bl[j][0], bl[j][1]);
                }
            }
        }
    }

    // epilogue: bias + relu, (optional) store h, plain + cw-weighted column sums
    float cw0[4], cw1[4];
    #pragma unroll
    for (int i = 0; i < 4; i++) {
        int r0 = m_block + wm * 64 + i * 16 + g;
        int r1 = r0 + 8;
        cw0[i] = (r0 < NN) ? g_cw[r0] : 0.f;
        cw1[i] = (r1 < NN) ? g_cw[r1] : 0.f;
    }
    #pragma unroll
    for (int j = 0; j < 4; j++) {
        int ncol = wn * 32 + j * 8 + 2 * tg;
        int n0 = n_block + ncol;
        float b0 = bias[n0], b1 = bias[n0 + 1];
        float cs0 = 0.f, cs1 = 0.f, ws0 = 0.f, ws1 = 0.f;
        #pragma unroll
        for (int i = 0; i < 4; i++) {
            int r0 = m_block + wm * 64 + i * 16 + g;
            int r1 = r0 + 8;
            if (r0 < NN) {
                float v0 = fmaxf(acc[i][j][0] + b0, 0.f);
                float v1 = fmaxf(acc[i][j][1] + b1, 0.f);
                if (store_h) *(float2*)(g_h + (size_t)r0 * DD + n0) = make_float2(v0, v1);
                cs0 += v0; cs1 += v1;
                ws0 += cw0[i] * v0; ws1 += cw0[i] * v1;
            }
            if (r1 < NN) {
                float v2 = fmaxf(acc[i][j][2] + b0, 0.f);
                float v3 = fmaxf(acc[i][j][3] + b1, 0.f);
                if (store_h) *(float2*)(g_h + (size_t)r1 * DD + n0) = make_float2(v2, v3);
                cs0 += v2; cs1 += v3;
                ws0 += cw1[i] * v2; ws1 += cw1[i] * v3;
            }
        }
        atomicAdd(&scol[ncol], cs0);
        atomicAdd(&scol[ncol + 1], cs1);
        atomicAdd(&scol2[ncol], ws0);
        atomicAdd(&scol2[ncol + 1], ws1);
    }
    __syncthreads();
    if (tid < 128) {
        atomicAdd(&g_colsum[n_block + tid], scol[tid]);
        atomicAdd(&g_s2[n_block + tid], scol2[tid]);
    }
}

// ---------------- agg2[var] from var's segment (graph 1 only) ----------------
__global__ void agg2var_kernel(const int* __restrict__ varp) {
    int var = *varp;
    int p0 = g_start[var], p1 = g_start[var + 1];
    float inv = g_inv[var];
    for (int d = threadIdx.x; d < DD; d += 256) {
        float s = 0.f;
        for (int p = p0; p < p1; p++)
            s += g_h[(size_t)g_sorted[p] * DD + d];
        g_agg2var[d] = s * inv;
    }
}

__global__ void rowvar_kernel(const int* __restrict__ varp) {
    int t = blockIdx.x * 256 + threadIdx.x;
    if (t < DD) g_rowvar[t] = g_h[(size_t)(*varp) * DD + t];
}

// ---------------- layer-2 matvecs ----------------
__global__ void matvec2_kernel(const float* __restrict__ Wl, const float* __restrict__ bias,
                               const float* __restrict__ Wr, int mode) {
    const float *a, *b; float s; float* out;
    if (mode == 0)      { a = g_s2;      b = g_colsum; s = 1.0f / NN; out = g_emb1; }
    else if (mode == 1) { a = g_agg2var; b = g_rowvar; s = 1.0f;      out = g_emb2; }
    else                { a = g_s2;      b = g_colsum; s = 1.0f / NN; out = g_embt; }
    int j = blockIdx.x, t = threadIdx.x;   // 128 threads
    const float* wl = Wl + (size_t)j * DD;
    const float* wr = Wr + (size_t)j * DD;
    float p = 0.f;
    for (int k = t; k < DD; k += 128) p += a[k] * wl[k] + b[k] * wr[k];
    #pragma unroll
    for (int o = 16; o; o >>= 1) p += __shfl_xor_sync(0xffffffffu, p, o);
    __shared__ float sw[4];
    if ((t & 31) == 0) sw[t >> 5] = p;
    __syncthreads();
    if (t == 0) out[j] = (sw[0] + sw[1] + sw[2] + sw[3]) * s + bias[j];
}

// ---------------- head ----------------
__global__ void feats_kernel() {
    int t = blockIdx.x * 256 + threadIdx.x;
    if (t < DD) {
        float a = g_emb1[t], b = g_emb2[t];
        g_feats[t] = a; g_feats[DD + t] = b; g_feats[2 * DD + t] = a * b;
    }
}

__global__ void out_kernel(const float* __restrict__ linW, const float* __restrict__ linb,
                           const float* __restrict__ Wo, const float* __restrict__ ov,
                           const int* __restrict__ opp, float* __restrict__ dout) {
    int j = blockIdx.x, t = threadIdx.x;   // 256 threads
    const float* w = linW + (size_t)j * (3 * DD);
    float p = 0.f;
    for (int k = t; k < 3 * DD; k += 256) p += w[k] * g_feats[k];
    #pragma unroll
    for (int o = 16; o; o >>= 1) p += __shfl_xor_sync(0xffffffffu, p, o);
    __shared__ float sw[8];
    if ((t & 31) == 0) sw[t >> 5] = p;
    __syncthreads();
    if (t == 0) {
        float tot = 0.f;
        #pragma unroll
        for (int i = 0; i < 8; i++) tot += sw[i];
        int op = *opp - 1;
        float o = (tot + linb[j]) * Wo[(size_t)op * DD + j];
        float tg = g_embt[j] + ov[(size_t)op * DD + j];
        g_outv[j] = o; g_tgt[j] = tg;
        dout[3 + j] = o;
    }
}

__global__ void final_kernel(const float* __restrict__ labels, float* __restrict__ dout) {
    int t = threadIdx.x;   // 256
    float dd = 0.f, no = 0.f, nt = 0.f;
    for (int j = t; j < DD; j += 256) {
        float o = g_outv[j], g = g_tgt[j];
        dd += o * g; no += o * o; nt += g * g;
    }
    #pragma unroll
    for (int o = 16; o; o >>= 1) {
        dd += __shfl_xor_sync(0xffffffffu, dd, o);
        no += __shfl_xor_sync(0xffffffffu, no, o);
        nt += __shfl_xor_sync(0xffffffffu, nt, o);
    }
    __shared__ float s0[8], s1[8], s2[8];
    if ((t & 31) == 0) { s0[t >> 5] = dd; s1[t >> 5] = no; s2[t >> 5] = nt; }
    __syncthreads();
    if (t == 0) {
        float D_ = 0.f, NO = 0.f, NT = 0.f;
        #pragma unroll
        for (int i = 0; i < 8; i++) { D_ += s0[i]; NO += s1[i]; NT += s2[i]; }
        float n1 = fmaxf(sqrtf(NO), 1e-8f);
        float n2 = fmaxf(sqrtf(NT), 1e-8f);
        float score = D_ / (n1 * n2);
        float lab = labels[0];
        float loss = (score - lab) * (score - lab);
        dout[0] = loss; dout[1] = score; dout[2] = lab;
    }
}

// ---------------- launch ----------------
extern "C" void kernel_launch(void* const* d_in, const int* in_sizes, int n_in,
                              void* d_out, int out_size) {
    (void)in_sizes; (void)n_in; (void)out_size;
    const float* x1   = (const float*)d_in[0];
    const int*   ei1  = (const int*)d_in[1];
    const int*   varp = (const int*)d_in[2];
    const float* xt   = (const float*)d_in[3];
    const int*   eit  = (const int*)d_in[4];
    const int*   opp  = (const int*)d_in[5];
    const float* labels = (const float*)d_in[6];
    const float* Wl1 = (const float*)d_in[7];
    const float* bl1 = (const float*)d_in[8];
    const float* Wr1 = (const float*)d_in[9];
    const float* Wl2 = (const float*)d_in[10];
    const float* bl2 = (const float*)d_in[11];
    const float* Wr2 = (const float*)d_in[12];
    const float* linW = (const float*)d_in[13];
    const float* linb = (const float*)d_in[14];
    const float* Wo  = (const float*)d_in[15];
    const float* ov  = (const float*)d_in[16];
    float* dout = (float*)d_out;

    cudaFuncSetAttribute(gemm_mma_kernel,
                         cudaFuncAttributeMaxDynamicSharedMemorySize, SMEM_GEMM);

    const int EB = (NE + 255) / 256;
    const int XB = ((NN * DD / 8) + 255) / 256;

    convert_b_kernel<<<(DD * K2 + 255) / 256, 256>>>(Wl1, Wr1);

    // ---- graph 1 ----
    zero_graph_kernel<<<118, 256>>>();
    count_kernel<<<EB, 256>>>(ei1);
    prefix_kernel<<<1, 1024>>>();
    place_kernel<<<EB, 256>>>(ei1);
    convert_x_kernel<<<XB, 256>>>(x1);
    gather_agg_kernel<<<dim3(3750, 6), 256>>>(x1);
    gemm_mma_kernel<<<dim3(6, 235), 256, SMEM_GEMM>>>(bl1, 1);
    agg2var_kernel<<<1, 256>>>(varp);
    rowvar_kernel<<<3, 256>>>(varp);
    matvec2_kernel<<<768, 128>>>(Wl2, bl2, Wr2, 0);   // emb1
    matvec2_kernel<<<768, 128>>>(Wl2, bl2, Wr2, 1);   // emb2

    // ---- graph t ----
    zero_graph_kernel<<<118, 256>>>();
    count_kernel<<<EB, 256>>>(eit);
    prefix_kernel<<<1, 1024>>>();
    place_kernel<<<EB, 256>>>(eit);
    convert_x_kernel<<<XB, 256>>>(xt);
    gather_agg_kernel<<<dim3(3750, 6), 256>>>(xt);
    gemm_mma_kernel<<<dim3(6, 235), 256, SMEM_GEMM>>>(bl1, 0);
    matvec2_kernel<<<768, 128>>>(Wl2, bl2, Wr2, 2);   // embt

    // ---- head ----
    feats_kernel<<<3, 256>>>();
    out_kernel<<<768, 256>>>(linW, linb, Wo, ov, opp, dout);
    final_kernel<<<1, 256>>>(labels, dout);
}